// round 1
// baseline (speedup 1.0000x reference)
#include <cuda_runtime.h>
#include <cuda_bf16.h>
#include <float.h>

// Problem constants (fixed shapes from metadata / reference)
#define BB   16
#define CC   256
#define HH   32
#define WW   32
#define NN   (BB * HH * WW)      // 16384 input vectors
#define KK   8192                // codebook size
#define HWN  (HH * WW)           // 1024
#define OUT_ELEMS   (BB * CC * HH * WW)   // 4194304
#define TOTAL_OUT   (OUT_ELEMS + 1 + NN)  // 4210689

#define QUANT_BLOCKS 4096

// Scratch (device globals — no allocation allowed)
__device__ float g_enorm[KK];
__device__ int   g_idx[NN];
__device__ float g_partial[QUANT_BLOCKS];

// ---------------------------------------------------------------------------
// Kernel 1: ||e_k||^2 for all K codes. One warp per row.
// ---------------------------------------------------------------------------
__global__ void enorm_kernel(const float* __restrict__ emb) {
    int row  = blockIdx.x * 8 + (threadIdx.x >> 5);
    int lane = threadIdx.x & 31;
    const float* e = emb + (size_t)row * CC;
    float s = 0.f;
#pragma unroll
    for (int i = 0; i < CC / 32; i++) {
        float v = __ldg(e + lane + i * 32);
        s += v * v;
    }
#pragma unroll
    for (int off = 16; off; off >>= 1)
        s += __shfl_xor_sync(0xffffffffu, s, off);
    if (lane == 0) g_enorm[row] = s;
}

// ---------------------------------------------------------------------------
// Kernel 2: fused SGEMM + argmin.
// Block: 256 threads, tile = 128 rows (input vecs) x 128 cols (codes),
// sweeping all 8192 codes. dist = ||e||^2 - 2 f.e  (||f||^2 constant per row).
// inputs layout: [B, C, H, W] -> flat[n][c] at inp[b*CC*HWN + c*HWN + rem],
// n = b*HWN + rem, so 128 consecutive n are contiguous in memory per fixed c.
// ---------------------------------------------------------------------------
__global__ __launch_bounds__(256, 1)
void argmin_kernel(const float* __restrict__ inp, const float* __restrict__ emb) {
    __shared__ float As[32][132];   // As[cc][n]   (padded: 16B-aligned rows, conflict-free)
    __shared__ float Bs[32][132];   // Bs[cc][k]

    const int tid = threadIdx.x;
    const int tx  = tid & 15;        // col group (8 cols each)
    const int ty  = tid >> 4;        // row group (8 rows each)

    const int rowBase = blockIdx.x * 128;
    const int b   = rowBase >> 10;        // rowBase / 1024
    const int rem = rowBase & 1023;
    const float* Abase = inp + (size_t)b * CC * HWN + rem;

    float best[8];
    int   bestk[8];
#pragma unroll
    for (int i = 0; i < 8; i++) { best[i] = FLT_MAX; bestk[i] = 0; }

    // A-load mapping: thread -> (cc = tid>>3, 16 consecutive n starting at (tid&7)*16)
    const int a_cc = tid >> 3;
    const int a_n0 = (tid & 7) * 16;
    // B-load mapping: thread -> (k = tid & 127, 16 consecutive c starting at (tid>>7)*16)
    const int b_k  = tid & 127;
    const int b_c0 = (tid >> 7) * 16;

    for (int colBase = 0; colBase < KK; colBase += 128) {
        float acc[8][8];
#pragma unroll
        for (int i = 0; i < 8; i++)
#pragma unroll
            for (int j = 0; j < 8; j++) acc[i][j] = 0.f;

        for (int cBase = 0; cBase < CC; cBase += 32) {
            // load A chunk: 32 c's x 128 n's
            {
                const float* ap = Abase + (size_t)(cBase + a_cc) * HWN + a_n0;
#pragma unroll
                for (int q = 0; q < 4; q++) {
                    float4 v = *(const float4*)(ap + q * 4);
                    *(float4*)&As[a_cc][a_n0 + q * 4] = v;
                }
            }
            // load B chunk: 128 k's x 32 c's, stored transposed Bs[c][k]
            {
                const float* bp = emb + (size_t)(colBase + b_k) * CC + cBase + b_c0;
#pragma unroll
                for (int q = 0; q < 4; q++) {
                    float4 v = *(const float4*)(bp + q * 4);
                    Bs[b_c0 + q * 4 + 0][b_k] = v.x;
                    Bs[b_c0 + q * 4 + 1][b_k] = v.y;
                    Bs[b_c0 + q * 4 + 2][b_k] = v.z;
                    Bs[b_c0 + q * 4 + 3][b_k] = v.w;
                }
            }
            __syncthreads();

#pragma unroll
            for (int cc2 = 0; cc2 < 32; cc2++) {
                float a[8], bb[8];
                *(float4*)&a[0]  = *(const float4*)&As[cc2][ty * 8];
                *(float4*)&a[4]  = *(const float4*)&As[cc2][ty * 8 + 4];
                *(float4*)&bb[0] = *(const float4*)&Bs[cc2][tx * 8];
                *(float4*)&bb[4] = *(const float4*)&Bs[cc2][tx * 8 + 4];
#pragma unroll
                for (int i = 0; i < 8; i++)
#pragma unroll
                    for (int j = 0; j < 8; j++)
                        acc[i][j] += a[i] * bb[j];
            }
            __syncthreads();
        }

        // Epilogue: dist = ||e||^2 - 2*dot; per-row min over 128 cols of this chunk.
        float colnorm[8];
#pragma unroll
        for (int j = 0; j < 8; j++)
            colnorm[j] = __ldg(&g_enorm[colBase + tx * 8 + j]);

#pragma unroll
        for (int i = 0; i < 8; i++) {
            float mv = FLT_MAX;
            int   mk = 0x7fffffff;
#pragma unroll
            for (int j = 0; j < 8; j++) {
                float d = fmaf(-2.f, acc[i][j], colnorm[j]);
                int   k = colBase + tx * 8 + j;
                if (d < mv) { mv = d; mk = k; }      // scan ascending -> first index kept
            }
            // butterfly min-reduce across the 16 tx lanes (all lanes get result)
#pragma unroll
            for (int off = 8; off; off >>= 1) {
                float ov = __shfl_xor_sync(0xffffffffu, mv, off, 16);
                int   ok = __shfl_xor_sync(0xffffffffu, mk, off, 16);
                if (ov < mv || (ov == mv && ok < mk)) { mv = ov; mk = ok; }
            }
            if (mv < best[i] || (mv == best[i] && mk < bestk[i])) {
                best[i] = mv; bestk[i] = mk;
            }
        }
    }

    if (tx == 0) {
#pragma unroll
        for (int i = 0; i < 8; i++)
            g_idx[rowBase + ty * 8 + i] = bestk[i];
    }
}

// ---------------------------------------------------------------------------
// Kernel 3: gather quantized output (already in [B,C,H,W] order since out and
// inputs share the same flat indexing) + per-block partial of sum((q-x)^2).
// ---------------------------------------------------------------------------
__global__ __launch_bounds__(256)
void quant_kernel(const float* __restrict__ inp, const float* __restrict__ emb,
                  float* __restrict__ out) {
    __shared__ float red[256];
    const int tid = threadIdx.x;
    const int p4  = blockIdx.x * 256 + tid;   // float4 index
    const int p   = p4 * 4;
    const int rem = p & 1023;
    const int c   = (p >> 10) & 255;
    const int b   = p >> 18;
    const int n   = b * HWN + rem;

    float4 x = *(const float4*)(inp + p);
    int k0 = g_idx[n + 0];
    int k1 = g_idx[n + 1];
    int k2 = g_idx[n + 2];
    int k3 = g_idx[n + 3];
    float q0 = __ldg(emb + (size_t)k0 * CC + c);
    float q1 = __ldg(emb + (size_t)k1 * CC + c);
    float q2 = __ldg(emb + (size_t)k2 * CC + c);
    float q3 = __ldg(emb + (size_t)k3 * CC + c);
    *(float4*)(out + p) = make_float4(q0, q1, q2, q3);

    float d0 = q0 - x.x, d1 = q1 - x.y, d2 = q2 - x.z, d3 = q3 - x.w;
    float s = d0 * d0 + d1 * d1 + d2 * d2 + d3 * d3;

    red[tid] = s;
    __syncthreads();
#pragma unroll
    for (int sft = 128; sft; sft >>= 1) {
        if (tid < sft) red[tid] += red[tid + sft];
        __syncthreads();
    }
    if (tid == 0) g_partial[blockIdx.x] = red[0];
}

// ---------------------------------------------------------------------------
// Kernel 4: deterministic final reduce -> loss; write idx as float.
// ---------------------------------------------------------------------------
__global__ __launch_bounds__(256)
void finalize_kernel(float* __restrict__ out, int out_size) {
    __shared__ float red[256];
    const int tid = threadIdx.x;
    float s = 0.f;
#pragma unroll
    for (int i = 0; i < QUANT_BLOCKS / 256; i++)
        s += g_partial[tid + i * 256];
    red[tid] = s;
    __syncthreads();
#pragma unroll
    for (int sft = 128; sft; sft >>= 1) {
        if (tid < sft) red[tid] += red[tid + sft];
        __syncthreads();
    }
    if (tid == 0 && out_size >= OUT_ELEMS + 1)
        out[OUT_ELEMS] = 0.25f * red[0] / (float)OUT_ELEMS;

    if (out_size >= TOTAL_OUT) {
        float* oi = out + OUT_ELEMS + 1;
        for (int i = tid; i < NN; i += 256)
            oi[i] = (float)g_idx[i];
    }
}

// ---------------------------------------------------------------------------
extern "C" void kernel_launch(void* const* d_in, const int* in_sizes, int n_in,
                              void* d_out, int out_size) {
    const float* inp = (const float*)d_in[0];
    const float* emb = (const float*)d_in[1];
    // defensive: identify operands by element count
    if (n_in >= 2 && in_sizes[0] == KK * CC && in_sizes[1] == NN * CC) {
        const float* t = inp; inp = emb; emb = t;
    }
    float* out = (float*)d_out;

    enorm_kernel<<<KK / 8, 256>>>(emb);
    argmin_kernel<<<NN / 128, 256>>>(inp, emb);
    quant_kernel<<<QUANT_BLOCKS, 256>>>(inp, emb, out);
    finalize_kernel<<<1, 256>>>(out, out_size);
}

// round 4
// speedup vs baseline: 1.8373x; 1.8373x over previous
#include <cuda_runtime.h>
#include <cuda_bf16.h>
#include <float.h>
#include <stdint.h>

// ---------------- problem constants ----------------
#define BB   16
#define CC   256
#define HWN  1024
#define NN   16384            // input vectors
#define KK   8192             // codebook size
#define OUT_ELEMS 4194304
#define TOTAL_OUT (OUT_ELEMS + 1 + NN)
#define QUANT_BLOCKS 4096

#define NCHUNKS 64            // 8192 / 128 codes per chunk
#define KCPN 24               // k-chunks (32 wide) per n-chunk: 768/32
#define TCHUNKS (NCHUNKS * KCPN)   // 1536

// ---------------- device scratch (no allocation allowed) ----------------
__device__ float g_enorm[KK];
__device__ int   g_idx[NN];
__device__ int2  g_cand[NN];
__device__ float g_partial[QUANT_BLOCKS];
__device__ __nv_bfloat16 g_eh[KK*CC], g_em[KK*CC];
__device__ __nv_bfloat16 g_ah[NN*CC], g_am[NN*CC];

// ---------------- PTX helpers (plain sm_103-legal only) ----------------
#define CP_ASYNC16(dst_u32, src_ptr) \
    asm volatile("cp.async.cg.shared.global [%0], [%1], 16;" \
        :: "r"(dst_u32), "l"(src_ptr) : "memory")
#define CP_COMMIT() asm volatile("cp.async.commit_group;" ::: "memory")
#define CP_WAIT(n)  asm volatile("cp.async.wait_group %0;" :: "n"(n) : "memory")

#define LDSM_X4(r0, r1, r2, r3, addr) \
    asm volatile("ldmatrix.sync.aligned.m8n8.x4.shared.b16 {%0,%1,%2,%3}, [%4];" \
        : "=r"(r0), "=r"(r1), "=r"(r2), "=r"(r3) : "r"(addr))

#define MMA_16816(c, a0, a1, a2, a3, b0, b1) \
    asm volatile("mma.sync.aligned.m16n8k16.row.col.f32.bf16.bf16.f32 " \
        "{%0,%1,%2,%3}, {%4,%5,%6,%7}, {%8,%9}, {%0,%1,%2,%3};" \
        : "+f"((c)[0]), "+f"((c)[1]), "+f"((c)[2]), "+f"((c)[3]) \
        : "r"(a0), "r"(a1), "r"(a2), "r"(a3), "r"(b0), "r"(b1))

// ---------------- SMEM layout ----------------
#define SA_OFF       0
#define A_ROW_BYTES  1536                      // 768 bf16, XOR-swizzled rows
#define SA_BYTES     (128 * A_ROW_BYTES)       // 196608
#define SB_OFF       SA_BYTES
#define B_ROW_BYTES  64                        // 32 bf16, 2-bit XOR swizzle
#define B_STAGE      (128 * B_ROW_BYTES)       // 8192
#define SP_V_OFF     (SB_OFF + 3 * B_STAGE)    // 221184
#define SP_I_OFF     (SP_V_OFF + 4096)         // pv: 128 rows x 4 wn x 2 cand
#define SMEM_TOTAL   (SP_I_OFF + 4096)         // 229376 (< 232448 opt-in max)

// B swizzle: byte-chunk q (16B units) XORed by bits 1..2 of the row
__device__ __forceinline__ uint32_t bswz(int row, int byt) {
    return (uint32_t)(row * B_ROW_BYTES + (byt ^ (((row >> 1) & 3) << 4)));
}

// =====================================================================
// Kernel 1: ||e_k||^2 (fp32 exact, from original embedding)
// =====================================================================
__global__ void enorm_kernel(const float* __restrict__ emb) {
    int row  = blockIdx.x * 8 + (threadIdx.x >> 5);
    int lane = threadIdx.x & 31;
    const float* e = emb + (size_t)row * CC;
    float s = 0.f;
#pragma unroll
    for (int i = 0; i < CC / 32; i++) { float v = __ldg(e + lane + i * 32); s += v * v; }
#pragma unroll
    for (int off = 16; off; off >>= 1) s += __shfl_xor_sync(0xffffffffu, s, off);
    if (lane == 0) g_enorm[row] = s;
}

// =====================================================================
// Kernel 2: bf16 2-level split of embedding ([k][c] K-major already)
// =====================================================================
__global__ void conv_emb_kernel(const float* __restrict__ emb) {
    int i = blockIdx.x * 256 + threadIdx.x;
    float x = emb[i];
    __nv_bfloat16 h = __float2bfloat16(x);
    float r1 = x - __bfloat162float(h);
    __nv_bfloat16 m = __float2bfloat16(r1);
    g_eh[i] = h; g_em[i] = m;
}

// =====================================================================
// Kernel 3: transpose inputs [B,C,HW] -> flat[n][c] + bf16 split
// =====================================================================
__global__ __launch_bounds__(256)
void conv_inp_kernel(const float* __restrict__ inp) {
    __shared__ float t[32][33];
    int n0 = blockIdx.x * 32;
    int c0 = blockIdx.y * 32;
    int b    = n0 >> 10;
    int rem0 = n0 & 1023;
    int tx = threadIdx.x & 31, ty = threadIdx.x >> 5;
#pragma unroll
    for (int i = 0; i < 4; i++) {
        int c = c0 + ty + i * 8;
        t[ty + i * 8][tx] = inp[(size_t)b * CC * HWN + (size_t)c * HWN + rem0 + tx];
    }
    __syncthreads();
#pragma unroll
    for (int i = 0; i < 4; i++) {
        int nl = ty + i * 8;
        int n = n0 + nl;
        float x = t[tx][nl];
        __nv_bfloat16 h = __float2bfloat16(x);
        float r1 = x - __bfloat162float(h);
        __nv_bfloat16 m = __float2bfloat16(r1);
        size_t o = (size_t)n * CC + c0 + tx;
        g_ah[o] = h; g_am[o] = m;
    }
}

// =====================================================================
// Kernel 4: fused mma.sync GEMM (K=768 bf16 split) + streaming top-2.
// 128 CTAs x 256 threads; A tile persistent in SMEM; B 3-stage cp.async.
// =====================================================================
__global__ __launch_bounds__(256, 1)
void vq_mma_kernel() {
    extern __shared__ char smc[];
    const uint32_t smem = (uint32_t)__cvta_generic_to_shared(smc);
    const int tid  = threadIdx.x;
    const int lane = tid & 31;
    const int warp = tid >> 5;
    const int wm = warp >> 2;          // 0..1  (m direction)
    const int wn = warp & 3;           // 0..3  (n direction)
    const int gid = lane >> 2, tig = lane & 3;
    const int rowBase = blockIdx.x * 128;

    // ---- prologue: A tile fill (128 x 768 bf16, swizzled rows) ----
    for (int i = 0; i < 48; i++) {
        int id  = tid + i * 256;
        int r   = id & 127;
        int q   = id >> 7;                       // 0..95 : 16B chunk (8 k-elems)
        int seg = q >> 5;                        // 0,1 -> fh ; 2 -> fm
        const __nv_bfloat16* src =
            (seg == 2 ? g_am : g_ah) + (size_t)(rowBase + r) * CC + (q & 31) * 8;
        uint32_t dst = smem + SA_OFF + r * A_ROW_BYTES + ((q * 16) ^ ((r & 7) << 4));
        CP_ASYNC16(dst, src);
    }
    CP_COMMIT();

    // ---- B chunk prefetch helper (chunk t: n-chunk t/24, k-chunk t%24) ----
    auto prefetchB = [&](int t) {
        int nc = t / KCPN, kc = t - nc * KCPN;
        int seg = kc >> 3;                       // 0:eh 1:em 2:eh
        const __nv_bfloat16* srcb = (seg == 1 ? g_em : g_eh);
        int kofs = (kc & 7) * 32;
        uint32_t sb = smem + SB_OFF + (t % 3) * B_STAGE;
#pragma unroll
        for (int j = 0; j < 2; j++) {
            int id = tid + j * 256;              // 0..511
            int n = id >> 2, q = id & 3;
            const __nv_bfloat16* src = srcb + (size_t)(nc * 128 + n) * CC + kofs + q * 8;
            CP_ASYNC16(sb + bswz(n, q * 16), src);
        }
    };
    prefetchB(0); CP_COMMIT();
    prefetchB(1); CP_COMMIT();

    float acc[4][4][4];
    float b1v = FLT_MAX, b2v = FLT_MAX;
    int   b1i = 0x7fffffff, b2i = 0x7fffffff;
    float* pv = (float*)(smc + SP_V_OFF);
    int*   pi = (int*)(smc + SP_I_OFF);

    for (int t = 0; t < TCHUNKS; t++) {
        if (t < TCHUNKS - 2) { CP_WAIT(1); } else { CP_WAIT(0); }
        __syncthreads();

        const int kc = t % KCPN;
        if (kc == 0) {
#pragma unroll
            for (int mf = 0; mf < 4; mf++)
#pragma unroll
                for (int nf = 0; nf < 4; nf++)
#pragma unroll
                    for (int e = 0; e < 4; e++) acc[mf][nf][e] = 0.f;
        }

        // ---- compute chunk t: 2 x k16 steps ----
        const uint32_t sb = smem + SB_OFF + (t % 3) * B_STAGE;
        const int kg = kc * 32;
#pragma unroll
        for (int s = 0; s < 2; s++) {
            uint32_t b[4][2];
#pragma unroll
            for (int h = 0; h < 2; h++) {
                int nrow = wn * 32 + h * 16 + (lane & 7) + ((lane >> 4) & 1) * 8;
                int byt  = s * 32 + ((lane >> 3) & 1) * 16;
                uint32_t addr = sb + bswz(nrow, byt);
                uint32_t q0, q1, q2, q3;
                LDSM_X4(q0, q1, q2, q3, addr);
                b[2*h][0] = q0; b[2*h][1] = q1; b[2*h+1][0] = q2; b[2*h+1][1] = q3;
            }
#pragma unroll
            for (int mf = 0; mf < 4; mf++) {
                int r = wm * 64 + mf * 16 + (lane & 7) + ((lane >> 3) & 1) * 8;
                int kbyte = (kg + s * 16) * 2 + ((lane >> 4) & 1) * 16;
                uint32_t addr = smem + SA_OFF + r * A_ROW_BYTES + (kbyte ^ ((r & 7) << 4));
                uint32_t a0, a1, a2, a3;
                LDSM_X4(a0, a1, a2, a3, addr);
#pragma unroll
                for (int nf = 0; nf < 4; nf++)
                    MMA_16816(acc[mf][nf], a0, a1, a2, a3, b[nf][0], b[nf][1]);
            }
        }

        if (t + 2 < TCHUNKS) { prefetchB(t + 2); CP_COMMIT(); }

        // ---- epilogue every 24 chunks: top-2 over this 128-code chunk ----
        if (kc == KCPN - 1) {
            const int nc = t / KCPN;
            const int colb = nc * 128 + wn * 32;
            float en[4][2];
#pragma unroll
            for (int nf = 0; nf < 4; nf++)
#pragma unroll
                for (int co = 0; co < 2; co++)
                    en[nf][co] = __ldg(&g_enorm[colb + nf * 8 + tig * 2 + co]);
#pragma unroll
            for (int mf = 0; mf < 4; mf++) {
#pragma unroll
                for (int half = 0; half < 2; half++) {
                    float v1 = FLT_MAX, v2 = FLT_MAX;
                    int   i1 = 0x7fffffff, i2 = 0x7fffffff;
#pragma unroll
                    for (int nf = 0; nf < 4; nf++)
#pragma unroll
                        for (int co = 0; co < 2; co++) {
                            float d = fmaf(-2.f, acc[mf][nf][half * 2 + co], en[nf][co]);
                            int ix = colb + nf * 8 + tig * 2 + co;
                            if (d < v1 || (d == v1 && ix < i1)) {
                                v2 = v1; i2 = i1; v1 = d; i1 = ix;
                            } else if (d < v2 || (d == v2 && ix < i2)) {
                                v2 = d; i2 = ix;
                            }
                        }
                    // merge top2 across the 4 tig lanes
#pragma unroll
                    for (int off = 1; off < 4; off <<= 1) {
                        float ov1 = __shfl_xor_sync(0xffffffffu, v1, off);
                        int   oi1 = __shfl_xor_sync(0xffffffffu, i1, off);
                        float ov2 = __shfl_xor_sync(0xffffffffu, v2, off);
                        int   oi2 = __shfl_xor_sync(0xffffffffu, i2, off);
                        if (ov1 < v1 || (ov1 == v1 && oi1 < i1)) {
                            v2 = v1; i2 = i1; v1 = ov1; i1 = oi1;
                        } else if (ov1 < v2 || (ov1 == v2 && oi1 < i2)) {
                            v2 = ov1; i2 = oi1;
                        }
                        if (ov2 < v2 || (ov2 == v2 && oi2 < i2)) { v2 = ov2; i2 = oi2; }
                    }
                    if (tig == 0) {
                        int row = wm * 64 + mf * 16 + half * 8 + gid;
                        pv[row * 8 + wn * 2 + 0] = v1;
                        pi[row * 8 + wn * 2 + 0] = i1;
                        pv[row * 8 + wn * 2 + 1] = v2;
                        pi[row * 8 + wn * 2 + 1] = i2;
                    }
                }
            }
            __syncthreads();
            if (tid < 128) {
#pragma unroll
                for (int w = 0; w < 8; w++) {
                    float v = pv[tid * 8 + w];
                    int   i = pi[tid * 8 + w];
                    if (v < b1v || (v == b1v && i < b1i)) {
                        b2v = b1v; b2i = b1i; b1v = v; b1i = i;
                    } else if (v < b2v || (v == b2v && i < b2i)) {
                        b2v = v; b2i = i;
                    }
                }
            }
        }
    }

    if (tid < 128) g_cand[rowBase + tid] = make_int2(b1i, b2i);
}

// =====================================================================
// Kernel 5: exact fp32 rescore of the two candidates per row.
// Bit-identical arithmetic to the R1-passing kernel: sequential fmaf
// chain over c ascending; dist = fmaf(-2, dot, enorm); lexicographic pick.
// =====================================================================
__global__ __launch_bounds__(256)
void rescore_kernel(const float* __restrict__ inp, const float* __restrict__ emb) {
    int n = blockIdx.x * 256 + threadIdx.x;
    int b = n >> 10, rem = n & 1023;
    const float* fbase = inp + (size_t)b * CC * HWN + rem;
    int2 cand = g_cand[n];
    const float* e0 = emb + (size_t)cand.x * CC;
    const float* e1 = emb + (size_t)cand.y * CC;
    float dot0 = 0.f, dot1 = 0.f;
#pragma unroll 8
    for (int c = 0; c < CC; c++) {
        float f = __ldg(fbase + (size_t)c * HWN);
        dot0 = fmaf(f, __ldg(e0 + c), dot0);
        dot1 = fmaf(f, __ldg(e1 + c), dot1);
    }
    float d0 = fmaf(-2.f, dot0, g_enorm[cand.x]);
    float d1 = fmaf(-2.f, dot1, g_enorm[cand.y]);
    int win = cand.x;
    if (d1 < d0 || (d1 == d0 && cand.y < cand.x)) win = cand.y;
    g_idx[n] = win;
}

// =====================================================================
// Kernel 6: gather quantized output + partial loss sums
// =====================================================================
__global__ __launch_bounds__(256)
void quant_kernel(const float* __restrict__ inp, const float* __restrict__ emb,
                  float* __restrict__ out) {
    __shared__ float red[256];
    const int tid = threadIdx.x;
    const int p4  = blockIdx.x * 256 + tid;
    const int p   = p4 * 4;
    const int rem = p & 1023;
    const int c   = (p >> 10) & 255;
    const int b   = p >> 18;
    const int n   = b * HWN + rem;

    float4 x = *(const float4*)(inp + p);
    int k0 = g_idx[n + 0], k1 = g_idx[n + 1], k2 = g_idx[n + 2], k3 = g_idx[n + 3];
    float q0 = __ldg(emb + (size_t)k0 * CC + c);
    float q1 = __ldg(emb + (size_t)k1 * CC + c);
    float q2 = __ldg(emb + (size_t)k2 * CC + c);
    float q3 = __ldg(emb + (size_t)k3 * CC + c);
    *(float4*)(out + p) = make_float4(q0, q1, q2, q3);

    float d0 = q0 - x.x, d1 = q1 - x.y, d2 = q2 - x.z, d3 = q3 - x.w;
    red[tid] = d0*d0 + d1*d1 + d2*d2 + d3*d3;
    __syncthreads();
#pragma unroll
    for (int sft = 128; sft; sft >>= 1) {
        if (tid < sft) red[tid] += red[tid + sft];
        __syncthreads();
    }
    if (tid == 0) g_partial[blockIdx.x] = red[0];
}

// =====================================================================
// Kernel 7: deterministic final reduce -> loss; idx as float
// =====================================================================
__global__ __launch_bounds__(256)
void finalize_kernel(float* __restrict__ out, int out_size) {
    __shared__ float red[256];
    const int tid = threadIdx.x;
    float s = 0.f;
#pragma unroll
    for (int i = 0; i < QUANT_BLOCKS / 256; i++) s += g_partial[tid + i * 256];
    red[tid] = s;
    __syncthreads();
#pragma unroll
    for (int sft = 128; sft; sft >>= 1) {
        if (tid < sft) red[tid] += red[tid + sft];
        __syncthreads();
    }
    if (tid == 0 && out_size >= OUT_ELEMS + 1)
        out[OUT_ELEMS] = 0.25f * red[0] / (float)OUT_ELEMS;
    if (out_size >= TOTAL_OUT) {
        float* oi = out + OUT_ELEMS + 1;
        for (int i = tid; i < NN; i += 256) oi[i] = (float)g_idx[i];
    }
}

// =====================================================================
extern "C" void kernel_launch(void* const* d_in, const int* in_sizes, int n_in,
                              void* d_out, int out_size) {
    const float* inp = (const float*)d_in[0];
    const float* emb = (const float*)d_in[1];
    if (n_in >= 2 && in_sizes[0] == KK * CC && in_sizes[1] == NN * CC) {
        const float* t = inp; inp = emb; emb = t;
    }
    float* out = (float*)d_out;

    cudaFuncSetAttribute(vq_mma_kernel,
                         cudaFuncAttributeMaxDynamicSharedMemorySize, SMEM_TOTAL);

    conv_emb_kernel<<<KK * CC / 256, 256>>>(emb);
    enorm_kernel<<<KK / 8, 256>>>(emb);
    {
        dim3 g(NN / 32, CC / 32);
        conv_inp_kernel<<<g, 256>>>(inp);
    }
    vq_mma_kernel<<<NN / 128, 256, SMEM_TOTAL>>>();
    rescore_kernel<<<NN / 256, 256>>>(inp, emb);
    quant_kernel<<<QUANT_BLOCKS, 256>>>(inp, emb, out);
    finalize_kernel<<<1, 256>>>(out, out_size);
}

// round 5
// speedup vs baseline: 2.2402x; 1.2193x over previous
#include <cuda_runtime.h>
#include <cuda_bf16.h>
#include <float.h>
#include <stdint.h>

// ---------------- problem constants ----------------
#define BB   16
#define CC   256
#define HWN  1024
#define NN   16384            // input vectors
#define KK   8192             // codebook size
#define OUT_ELEMS 4194304
#define TOTAL_OUT (OUT_ELEMS + 1 + NN)
#define QUANT_BLOCKS 4096

#define NCHUNKS 64            // 8192 / 128 codes per chunk
#define KCPN 24               // k-chunks (32 wide) per n-chunk: 768/32
#define TCHUNKS (NCHUNKS * KCPN)   // 1536

// ---------------- device scratch (no allocation allowed) ----------------
__device__ float g_enorm[KK];
__device__ int   g_idx[NN];
__device__ int2  g_cand[NN];
__device__ float g_partial[QUANT_BLOCKS];
__device__ __nv_bfloat16 g_eh[KK*CC], g_em[KK*CC];
__device__ __nv_bfloat16 g_ah[NN*CC], g_am[NN*CC];

// ---------------- PTX helpers (plain sm_103-legal only) ----------------
#define CP_ASYNC16(dst_u32, src_ptr) \
    asm volatile("cp.async.cg.shared.global [%0], [%1], 16;" \
        :: "r"(dst_u32), "l"(src_ptr) : "memory")
#define CP_COMMIT() asm volatile("cp.async.commit_group;" ::: "memory")
#define CP_WAIT(n)  asm volatile("cp.async.wait_group %0;" :: "n"(n) : "memory")

#define LDSM_X4(r0, r1, r2, r3, addr) \
    asm volatile("ldmatrix.sync.aligned.m8n8.x4.shared.b16 {%0,%1,%2,%3}, [%4];" \
        : "=r"(r0), "=r"(r1), "=r"(r2), "=r"(r3) : "r"(addr))

#define MMA_16816(c, a0, a1, a2, a3, b0, b1) \
    asm volatile("mma.sync.aligned.m16n8k16.row.col.f32.bf16.bf16.f32 " \
        "{%0,%1,%2,%3}, {%4,%5,%6,%7}, {%8,%9}, {%0,%1,%2,%3};" \
        : "+f"((c)[0]), "+f"((c)[1]), "+f"((c)[2]), "+f"((c)[3]) \
        : "r"(a0), "r"(a1), "r"(a2), "r"(a3), "r"(b0), "r"(b1))

#define PAIR_BAR(wn) \
    asm volatile("bar.sync %0, %1;" :: "r"((wn) + 1), "r"(64) : "memory")

// ---------------- SMEM layout ----------------
#define SA_OFF       0
#define A_ROW_BYTES  1536                      // 768 bf16, XOR-swizzled rows
#define SA_BYTES     (128 * A_ROW_BYTES)       // 196608
#define SB_OFF       SA_BYTES
#define B_ROW_BYTES  64                        // 32 bf16, 2-bit XOR swizzle
#define B_STAGE      (128 * B_ROW_BYTES)       // 8192
#define SMEM_TOTAL   (SB_OFF + 3 * B_STAGE)    // 221184 (< 232448 opt-in max)
// final merge partials reuse the B-stage area (B is dead by then):
//   pv: 128 rows x 4 wn x 2 cand floats (4096 B) at SB_OFF
//   pi: same size ints at SB_OFF + 4096

// B swizzle: byte-chunk (16B units) XORed by bits 1..2 of the row
__device__ __forceinline__ uint32_t bswz(int row, int byt) {
    return (uint32_t)(row * B_ROW_BYTES + (byt ^ (((row >> 1) & 3) << 4)));
}

// =====================================================================
// Kernel 1: ||e_k||^2 (fp32 exact, from original embedding)
// =====================================================================
__global__ void enorm_kernel(const float* __restrict__ emb) {
    int row  = blockIdx.x * 8 + (threadIdx.x >> 5);
    int lane = threadIdx.x & 31;
    const float* e = emb + (size_t)row * CC;
    float s = 0.f;
#pragma unroll
    for (int i = 0; i < CC / 32; i++) { float v = __ldg(e + lane + i * 32); s += v * v; }
#pragma unroll
    for (int off = 16; off; off >>= 1) s += __shfl_xor_sync(0xffffffffu, s, off);
    if (lane == 0) g_enorm[row] = s;
}

// =====================================================================
// Kernel 2: bf16 2-level split of embedding ([k][c] K-major already)
// =====================================================================
__global__ void conv_emb_kernel(const float* __restrict__ emb) {
    int i = blockIdx.x * 256 + threadIdx.x;
    float x = emb[i];
    __nv_bfloat16 h = __float2bfloat16(x);
    float r1 = x - __bfloat162float(h);
    __nv_bfloat16 m = __float2bfloat16(r1);
    g_eh[i] = h; g_em[i] = m;
}

// =====================================================================
// Kernel 3: transpose inputs [B,C,HW] -> flat[n][c] + bf16 split
// =====================================================================
__global__ __launch_bounds__(256)
void conv_inp_kernel(const float* __restrict__ inp) {
    __shared__ float t[32][33];
    int n0 = blockIdx.x * 32;
    int c0 = blockIdx.y * 32;
    int b    = n0 >> 10;
    int rem0 = n0 & 1023;
    int tx = threadIdx.x & 31, ty = threadIdx.x >> 5;
#pragma unroll
    for (int i = 0; i < 4; i++) {
        int c = c0 + ty + i * 8;
        t[ty + i * 8][tx] = inp[(size_t)b * CC * HWN + (size_t)c * HWN + rem0 + tx];
    }
    __syncthreads();
#pragma unroll
    for (int i = 0; i < 4; i++) {
        int nl = ty + i * 8;
        int n = n0 + nl;
        float x = t[tx][nl];
        __nv_bfloat16 h = __float2bfloat16(x);
        float r1 = x - __bfloat162float(h);
        __nv_bfloat16 m = __float2bfloat16(r1);
        size_t o = (size_t)n * CC + c0 + tx;
        g_ah[o] = h; g_am[o] = m;
    }
}

// =====================================================================
// Kernel 4: fused mma.sync GEMM (K=768 bf16 split) + persistent top-2.
// 128 CTAs x 256 threads. A tile persistent in SMEM. B 3-stage cp.async
// ring with PAIR-LOCAL loading + named pair barriers (no block-wide sync
// in the mainloop). Warp map: wm = warp&1 (M), wn = warp>>1 (N), so each
// SMSP hosts warps of two different pairs.
// =====================================================================
__global__ __launch_bounds__(256, 1)
void vq_mma_kernel() {
    extern __shared__ char smc[];
    const uint32_t smem = (uint32_t)__cvta_generic_to_shared(smc);
    const int tid  = threadIdx.x;
    const int lane = tid & 31;
    const int warp = tid >> 5;
    const int wm = warp & 1;           // 0..1  (m direction)
    const int wn = warp >> 1;          // 0..3  (n direction)
    const int gid = lane >> 2, tig = lane & 3;
    const int ltid = tid & 63;         // thread id within the pair
    const int rowBase = blockIdx.x * 128;

    // ---- prologue: A tile fill (128 x 768 bf16, swizzled rows) ----
    for (int i = 0; i < 48; i++) {
        int id  = tid + i * 256;
        int r   = id & 127;
        int q   = id >> 7;                       // 0..95 : 16B chunk (8 k-elems)
        int seg = q >> 5;                        // 0,1 -> fh ; 2 -> fm
        const __nv_bfloat16* src =
            (seg == 2 ? g_am : g_ah) + (size_t)(rowBase + r) * CC + (q & 31) * 8;
        uint32_t dst = smem + SA_OFF + r * A_ROW_BYTES + ((q * 16) ^ ((r & 7) << 4));
        CP_ASYNC16(dst, src);
    }
    CP_COMMIT();

    // ---- pair-local B prefetch: pair wn loads rows [wn*32, wn*32+32) ----
    auto prefetchB = [&](int t) {
        int nc = t / KCPN, kc = t - nc * KCPN;
        int seg = kc >> 3;                       // 0:eh 1:em 2:eh
        const __nv_bfloat16* srcb = (seg == 1 ? g_em : g_eh);
        int kofs = (kc & 7) * 32;
        uint32_t sb = smem + SB_OFF + (t % 3) * B_STAGE;
        int n  = wn * 32 + (ltid >> 1);          // this pair's slice
        int q0 = (ltid & 1) * 2;
#pragma unroll
        for (int j = 0; j < 2; j++) {
            int q = q0 + j;
            const __nv_bfloat16* src = srcb + (size_t)(nc * 128 + n) * CC + kofs + q * 8;
            CP_ASYNC16(sb + bswz(n, q * 16), src);
        }
    };
    prefetchB(0); CP_COMMIT();
    prefetchB(1); CP_COMMIT();
    CP_WAIT(1);                 // A + B0 complete
    __syncthreads();            // A visible to all warps

    float acc[4][4][4];
    // persistent per-lane top-2 per (mf, half)
    float tv1[4][2], tv2[4][2];
    int   ti1[4][2], ti2[4][2];
#pragma unroll
    for (int mf = 0; mf < 4; mf++)
#pragma unroll
        for (int hf = 0; hf < 2; hf++) {
            tv1[mf][hf] = FLT_MAX; tv2[mf][hf] = FLT_MAX;
            ti1[mf][hf] = 0x7fffffff; ti2[mf][hf] = 0x7fffffff;
        }

    for (int t = 0; t < TCHUNKS; t++) {
        if (t > 0) {
            if (t == TCHUNKS - 1) { CP_WAIT(0); } else { CP_WAIT(1); }
            PAIR_BAR(wn);
        }
        if (t + 2 < TCHUNKS) { prefetchB(t + 2); CP_COMMIT(); }

        const int kc = t % KCPN;
        if (kc == 0) {
#pragma unroll
            for (int mf = 0; mf < 4; mf++)
#pragma unroll
                for (int nf = 0; nf < 4; nf++)
#pragma unroll
                    for (int e = 0; e < 4; e++) acc[mf][nf][e] = 0.f;
        }

        // ---- compute chunk t: 2 x k16 steps ----
        const uint32_t sb = smem + SB_OFF + (t % 3) * B_STAGE;
        const int kg = kc * 32;
#pragma unroll
        for (int s = 0; s < 2; s++) {
            uint32_t b[4][2];
#pragma unroll
            for (int h = 0; h < 2; h++) {
                int nrow = wn * 32 + h * 16 + (lane & 7) + ((lane >> 4) & 1) * 8;
                int byt  = s * 32 + ((lane >> 3) & 1) * 16;
                uint32_t addr = sb + bswz(nrow, byt);
                uint32_t q0, q1, q2, q3;
                LDSM_X4(q0, q1, q2, q3, addr);
                b[2*h][0] = q0; b[2*h][1] = q1; b[2*h+1][0] = q2; b[2*h+1][1] = q3;
            }
#pragma unroll
            for (int mf = 0; mf < 4; mf++) {
                int r = wm * 64 + mf * 16 + (lane & 7) + ((lane >> 3) & 1) * 8;
                int kbyte = (kg + s * 16) * 2 + ((lane >> 4) & 1) * 16;
                uint32_t addr = smem + SA_OFF + r * A_ROW_BYTES + (kbyte ^ ((r & 7) << 4));
                uint32_t a0, a1, a2, a3;
                LDSM_X4(a0, a1, a2, a3, addr);
#pragma unroll
                for (int nf = 0; nf < 4; nf++)
                    MMA_16816(acc[mf][nf], a0, a1, a2, a3, b[nf][0], b[nf][1]);
            }
        }

        // ---- end of n-chunk: fold 128-code chunk into persistent top-2 ----
        if (kc == KCPN - 1) {
            const int nc = t / KCPN;
            const int colb = nc * 128 + wn * 32;
            float en[4][2];
#pragma unroll
            for (int nf = 0; nf < 4; nf++)
#pragma unroll
                for (int co = 0; co < 2; co++)
                    en[nf][co] = __ldg(&g_enorm[colb + nf * 8 + tig * 2 + co]);
#pragma unroll
            for (int mf = 0; mf < 4; mf++)
#pragma unroll
                for (int hf = 0; hf < 2; hf++) {
                    float v1 = tv1[mf][hf], v2 = tv2[mf][hf];
                    int   i1 = ti1[mf][hf], i2 = ti2[mf][hf];
#pragma unroll
                    for (int nf = 0; nf < 4; nf++)
#pragma unroll
                        for (int co = 0; co < 2; co++) {
                            float d = fmaf(-2.f, acc[mf][nf][hf * 2 + co], en[nf][co]);
                            int ix = colb + nf * 8 + tig * 2 + co;
                            if (d < v1 || (d == v1 && ix < i1)) {
                                v2 = v1; i2 = i1; v1 = d; i1 = ix;
                            } else if (d < v2 || (d == v2 && ix < i2)) {
                                v2 = d; i2 = ix;
                            }
                        }
                    tv1[mf][hf] = v1; tv2[mf][hf] = v2;
                    ti1[mf][hf] = i1; ti2[mf][hf] = i2;
                }
        }
    }

    // ---- final merge: across tig lanes, then across wn via SMEM ----
    __syncthreads();                 // all pairs done; B stages now reusable
    float* pv = (float*)(smc + SB_OFF);
    int*   pi = (int*)(smc + SB_OFF + 4096);
#pragma unroll
    for (int mf = 0; mf < 4; mf++)
#pragma unroll
        for (int hf = 0; hf < 2; hf++) {
            float v1 = tv1[mf][hf], v2 = tv2[mf][hf];
            int   i1 = ti1[mf][hf], i2 = ti2[mf][hf];
#pragma unroll
            for (int off = 1; off < 4; off <<= 1) {
                float ov1 = __shfl_xor_sync(0xffffffffu, v1, off);
                int   oi1 = __shfl_xor_sync(0xffffffffu, i1, off);
                float ov2 = __shfl_xor_sync(0xffffffffu, v2, off);
                int   oi2 = __shfl_xor_sync(0xffffffffu, i2, off);
                if (ov1 < v1 || (ov1 == v1 && oi1 < i1)) {
                    v2 = v1; i2 = i1; v1 = ov1; i1 = oi1;
                } else if (ov1 < v2 || (ov1 == v2 && oi1 < i2)) {
                    v2 = ov1; i2 = oi1;
                }
                if (ov2 < v2 || (ov2 == v2 && oi2 < i2)) { v2 = ov2; i2 = oi2; }
            }
            if (tig == 0) {
                int row = wm * 64 + mf * 16 + hf * 8 + gid;
                pv[row * 8 + wn * 2 + 0] = v1;
                pi[row * 8 + wn * 2 + 0] = i1;
                pv[row * 8 + wn * 2 + 1] = v2;
                pi[row * 8 + wn * 2 + 1] = i2;
            }
        }
    __syncthreads();
    if (tid < 128) {
        float b1v = FLT_MAX, b2v = FLT_MAX;
        int   b1i = 0x7fffffff, b2i = 0x7fffffff;
#pragma unroll
        for (int w = 0; w < 8; w++) {
            float v = pv[tid * 8 + w];
            int   i = pi[tid * 8 + w];
            if (v < b1v || (v == b1v && i < b1i)) {
                b2v = b1v; b2i = b1i; b1v = v; b1i = i;
            } else if (v < b2v || (v == b2v && i < b2i)) {
                b2v = v; b2i = i;
            }
        }
        g_cand[rowBase + tid] = make_int2(b1i, b2i);
    }
}

// =====================================================================
// Kernel 5: exact fp32 rescore of the two candidates per row.
// Bit-identical arithmetic to the R1-passing kernel.
// =====================================================================
__global__ __launch_bounds__(256)
void rescore_kernel(const float* __restrict__ inp, const float* __restrict__ emb) {
    int n = blockIdx.x * 256 + threadIdx.x;
    int b = n >> 10, rem = n & 1023;
    const float* fbase = inp + (size_t)b * CC * HWN + rem;
    int2 cand = g_cand[n];
    const float* e0 = emb + (size_t)cand.x * CC;
    const float* e1 = emb + (size_t)cand.y * CC;
    float dot0 = 0.f, dot1 = 0.f;
#pragma unroll 8
    for (int c = 0; c < CC; c++) {
        float f = __ldg(fbase + (size_t)c * HWN);
        dot0 = fmaf(f, __ldg(e0 + c), dot0);
        dot1 = fmaf(f, __ldg(e1 + c), dot1);
    }
    float d0 = fmaf(-2.f, dot0, g_enorm[cand.x]);
    float d1 = fmaf(-2.f, dot1, g_enorm[cand.y]);
    int win = cand.x;
    if (d1 < d0 || (d1 == d0 && cand.y < cand.x)) win = cand.y;
    g_idx[n] = win;
}

// =====================================================================
// Kernel 6: gather quantized output + partial loss sums
// =====================================================================
__global__ __launch_bounds__(256)
void quant_kernel(const float* __restrict__ inp, const float* __restrict__ emb,
                  float* __restrict__ out) {
    __shared__ float red[256];
    const int tid = threadIdx.x;
    const int p4  = blockIdx.x * 256 + tid;
    const int p   = p4 * 4;
    const int rem = p & 1023;
    const int c   = (p >> 10) & 255;
    const int b   = p >> 18;
    const int n   = b * HWN + rem;

    float4 x = *(const float4*)(inp + p);
    int k0 = g_idx[n + 0], k1 = g_idx[n + 1], k2 = g_idx[n + 2], k3 = g_idx[n + 3];
    float q0 = __ldg(emb + (size_t)k0 * CC + c);
    float q1 = __ldg(emb + (size_t)k1 * CC + c);
    float q2 = __ldg(emb + (size_t)k2 * CC + c);
    float q3 = __ldg(emb + (size_t)k3 * CC + c);
    *(float4*)(out + p) = make_float4(q0, q1, q2, q3);

    float d0 = q0 - x.x, d1 = q1 - x.y, d2 = q2 - x.z, d3 = q3 - x.w;
    red[tid] = d0*d0 + d1*d1 + d2*d2 + d3*d3;
    __syncthreads();
#pragma unroll
    for (int sft = 128; sft; sft >>= 1) {
        if (tid < sft) red[tid] += red[tid + sft];
        __syncthreads();
    }
    if (tid == 0) g_partial[blockIdx.x] = red[0];
}

// =====================================================================
// Kernel 7: deterministic final reduce -> loss; idx as float
// =====================================================================
__global__ __launch_bounds__(256)
void finalize_kernel(float* __restrict__ out, int out_size) {
    __shared__ float red[256];
    const int tid = threadIdx.x;
    float s = 0.f;
#pragma unroll
    for (int i = 0; i < QUANT_BLOCKS / 256; i++) s += g_partial[tid + i * 256];
    red[tid] = s;
    __syncthreads();
#pragma unroll
    for (int sft = 128; sft; sft >>= 1) {
        if (tid < sft) red[tid] += red[tid + sft];
        __syncthreads();
    }
    if (tid == 0 && out_size >= OUT_ELEMS + 1)
        out[OUT_ELEMS] = 0.25f * red[0] / (float)OUT_ELEMS;
    if (out_size >= TOTAL_OUT) {
        float* oi = out + OUT_ELEMS + 1;
        for (int i = tid; i < NN; i += 256) oi[i] = (float)g_idx[i];
    }
}

// =====================================================================
extern "C" void kernel_launch(void* const* d_in, const int* in_sizes, int n_in,
                              void* d_out, int out_size) {
    const float* inp = (const float*)d_in[0];
    const float* emb = (const float*)d_in[1];
    if (n_in >= 2 && in_sizes[0] == KK * CC && in_sizes[1] == NN * CC) {
        const float* t = inp; inp = emb; emb = t;
    }
    float* out = (float*)d_out;

    cudaFuncSetAttribute(vq_mma_kernel,
                         cudaFuncAttributeMaxDynamicSharedMemorySize, SMEM_TOTAL);

    conv_emb_kernel<<<KK * CC / 256, 256>>>(emb);
    enorm_kernel<<<KK / 8, 256>>>(emb);
    {
        dim3 g(NN / 32, CC / 32);
        conv_inp_kernel<<<g, 256>>>(inp);
    }
    vq_mma_kernel<<<NN / 128, 256, SMEM_TOTAL>>>();
    rescore_kernel<<<NN / 256, 256>>>(inp, emb);
    quant_kernel<<<QUANT_BLOCKS, 256>>>(inp, emb, out);
    finalize_kernel<<<1, 256>>>(out, out_size);
}

// round 6
// speedup vs baseline: 2.4000x; 1.0714x over previous
#include <cuda_runtime.h>
#include <cuda_bf16.h>
#include <float.h>
#include <stdint.h>

// ---------------- problem constants ----------------
#define BB   16
#define CC   256
#define HWN  1024
#define NN   16384            // input vectors
#define KK   8192             // codebook size
#define OUT_ELEMS 4194304
#define TOTAL_OUT (OUT_ELEMS + 1 + NN)
#define QUANT_BLOCKS 4096

#define NCHUNKS 64            // 8192 / 128 codes per chunk
#define KCPN 24               // k-chunks (32 wide) per n-chunk: 768/32
#define TCHUNKS (NCHUNKS * KCPN)   // 1536

// ---------------- device scratch (no allocation allowed) ----------------
__device__ float g_enorm[KK];
__device__ int   g_idx[NN];
__device__ int2  g_cand[NN];
__device__ float g_partial[QUANT_BLOCKS];
__device__ __nv_bfloat16 g_eh[KK*CC], g_em[KK*CC];
__device__ __nv_bfloat16 g_ah[NN*CC], g_am[NN*CC];

// ---------------- PTX helpers (plain sm_103-legal only) ----------------
#define CP_ASYNC16(dst_u32, src_ptr) \
    asm volatile("cp.async.cg.shared.global [%0], [%1], 16;" \
        :: "r"(dst_u32), "l"(src_ptr) : "memory")
#define CP_COMMIT() asm volatile("cp.async.commit_group;" ::: "memory")
#define CP_WAIT(n)  asm volatile("cp.async.wait_group %0;" :: "n"(n) : "memory")

#define LDSM_X4(r0, r1, r2, r3, addr) \
    asm volatile("ldmatrix.sync.aligned.m8n8.x4.shared.b16 {%0,%1,%2,%3}, [%4];" \
        : "=r"(r0), "=r"(r1), "=r"(r2), "=r"(r3) : "r"(addr))

#define MMA_16816(c, a0, a1, a2, a3, b0, b1) \
    asm volatile("mma.sync.aligned.m16n8k16.row.col.f32.bf16.bf16.f32 " \
        "{%0,%1,%2,%3}, {%4,%5,%6,%7}, {%8,%9}, {%0,%1,%2,%3};" \
        : "+f"((c)[0]), "+f"((c)[1]), "+f"((c)[2]), "+f"((c)[3]) \
        : "r"(a0), "r"(a1), "r"(a2), "r"(a3), "r"(b0), "r"(b1))

#define GROUP_BAR(wn) \
    asm volatile("bar.sync %0, %1;" :: "r"((wn) + 1), "r"(128) : "memory")

// ---------------- SMEM layout ----------------
#define SA_OFF       0
#define A_ROW_BYTES  1536                      // 768 bf16, XOR-swizzled rows
#define SA_BYTES     (128 * A_ROW_BYTES)       // 196608
#define SB_OFF       SA_BYTES
#define B_ROW_BYTES  64                        // 32 bf16, 2-bit XOR swizzle
#define B_STAGE      (128 * B_ROW_BYTES)       // 8192
#define SMEM_TOTAL   (SB_OFF + 3 * B_STAGE)    // 221184 (< 232448 opt-in max)
// final merge partials reuse the B-stage area (B is dead by then)

// B swizzle: byte-chunk (16B units) XORed by bits 1..2 of the row
__device__ __forceinline__ uint32_t bswz(int row, int byt) {
    return (uint32_t)(row * B_ROW_BYTES + (byt ^ (((row >> 1) & 3) << 4)));
}

// =====================================================================
// Kernel 1: embedding prep — bf16 2-level split AND ||e_k||^2.
// One warp per row; enorm arithmetic identical to the R1-exact kernel.
// =====================================================================
__global__ __launch_bounds__(256)
void emb_prep_kernel(const float* __restrict__ emb) {
    int row  = blockIdx.x * 8 + (threadIdx.x >> 5);
    int lane = threadIdx.x & 31;
    const float* e = emb + (size_t)row * CC;
    float s = 0.f;
#pragma unroll
    for (int i = 0; i < CC / 32; i++) {
        int c = lane + i * 32;
        float v = __ldg(e + c);
        s += v * v;
        __nv_bfloat16 h = __float2bfloat16(v);
        float r1 = v - __bfloat162float(h);
        __nv_bfloat16 m = __float2bfloat16(r1);
        size_t o = (size_t)row * CC + c;
        g_eh[o] = h; g_em[o] = m;
    }
#pragma unroll
    for (int off = 16; off; off >>= 1) s += __shfl_xor_sync(0xffffffffu, s, off);
    if (lane == 0) g_enorm[row] = s;
}

// =====================================================================
// Kernel 2: transpose inputs [B,C,HW] -> flat[n][c] + bf16 split
// =====================================================================
__global__ __launch_bounds__(256)
void conv_inp_kernel(const float* __restrict__ inp) {
    __shared__ float t[32][33];
    int n0 = blockIdx.x * 32;
    int c0 = blockIdx.y * 32;
    int b    = n0 >> 10;
    int rem0 = n0 & 1023;
    int tx = threadIdx.x & 31, ty = threadIdx.x >> 5;
#pragma unroll
    for (int i = 0; i < 4; i++) {
        int c = c0 + ty + i * 8;
        t[ty + i * 8][tx] = inp[(size_t)b * CC * HWN + (size_t)c * HWN + rem0 + tx];
    }
    __syncthreads();
#pragma unroll
    for (int i = 0; i < 4; i++) {
        int nl = ty + i * 8;
        int n = n0 + nl;
        float x = t[tx][nl];
        __nv_bfloat16 h = __float2bfloat16(x);
        float r1 = x - __bfloat162float(h);
        __nv_bfloat16 m = __float2bfloat16(r1);
        size_t o = (size_t)n * CC + c0 + tx;
        g_ah[o] = h; g_am[o] = m;
    }
}

// =====================================================================
// Kernel 3: fused mma.sync GEMM (K=768 bf16 split) + persistent top-2.
// 128 CTAs x 512 threads (16 warps, 4/SMSP). Warp map: wm = warp&3
// (= SMSP), wn = warp>>2 — each SMSP hosts 4 warps from 4 different
// wn groups, so group barriers overlap with other groups' compute.
// B: 3-stage cp.async ring, GROUP-LOCAL loading + named group barriers.
// =====================================================================
__global__ __launch_bounds__(512, 1)
void vq_mma_kernel() {
    extern __shared__ char smc[];
    const uint32_t smem = (uint32_t)__cvta_generic_to_shared(smc);
    const int tid  = threadIdx.x;
    const int lane = tid & 31;
    const int warp = tid >> 5;
    const int wm = warp & 3;           // 0..3  (M direction, = SMSP)
    const int wn = warp >> 2;          // 0..3  (N direction, = group)
    const int gid = lane >> 2, tig = lane & 3;
    const int ltid = tid & 127;        // thread id within the group
    const int rowBase = blockIdx.x * 128;

    // ---- prologue: A tile fill (128 x 768 bf16, swizzled rows) ----
    for (int i = 0; i < 24; i++) {
        int id  = tid + i * 512;
        int r   = id & 127;
        int q   = id >> 7;                       // 0..95 : 16B chunk (8 k-elems)
        int seg = q >> 5;                        // 0,1 -> fh ; 2 -> fm
        const __nv_bfloat16* src =
            (seg == 2 ? g_am : g_ah) + (size_t)(rowBase + r) * CC + (q & 31) * 8;
        uint32_t dst = smem + SA_OFF + r * A_ROW_BYTES + ((q * 16) ^ ((r & 7) << 4));
        CP_ASYNC16(dst, src);
    }
    CP_COMMIT();

    // ---- group-local B prefetch: group wn loads rows [wn*32, wn*32+32) ----
    auto prefetchB = [&](int t) {
        int nc = t / KCPN, kc = t - nc * KCPN;
        int seg = kc >> 3;                       // 0:eh 1:em 2:eh
        const __nv_bfloat16* srcb = (seg == 1 ? g_em : g_eh);
        int kofs = (kc & 7) * 32;
        uint32_t sb = smem + SB_OFF + (t % 3) * B_STAGE;
        int n = wn * 32 + (ltid >> 2);           // this group's slice
        int q = ltid & 3;
        const __nv_bfloat16* src = srcb + (size_t)(nc * 128 + n) * CC + kofs + q * 8;
        CP_ASYNC16(sb + bswz(n, q * 16), src);
    };
    prefetchB(0); CP_COMMIT();
    prefetchB(1); CP_COMMIT();
    CP_WAIT(1);                 // A + B0 complete
    __syncthreads();            // A visible to all warps

    float acc[2][4][4];
    // persistent per-lane top-2 per (mf, half)
    float tv1[2][2], tv2[2][2];
    int   ti1[2][2], ti2[2][2];
#pragma unroll
    for (int mf = 0; mf < 2; mf++)
#pragma unroll
        for (int hf = 0; hf < 2; hf++) {
            tv1[mf][hf] = FLT_MAX; tv2[mf][hf] = FLT_MAX;
            ti1[mf][hf] = 0x7fffffff; ti2[mf][hf] = 0x7fffffff;
        }

    for (int t = 0; t < TCHUNKS; t++) {
        if (t > 0) {
            if (t == TCHUNKS - 1) { CP_WAIT(0); } else { CP_WAIT(1); }
            GROUP_BAR(wn);
        }
        if (t + 2 < TCHUNKS) { prefetchB(t + 2); CP_COMMIT(); }

        const int kc = t % KCPN;
        if (kc == 0) {
#pragma unroll
            for (int mf = 0; mf < 2; mf++)
#pragma unroll
                for (int nf = 0; nf < 4; nf++)
#pragma unroll
                    for (int e = 0; e < 4; e++) acc[mf][nf][e] = 0.f;
        }

        // ---- compute chunk t: 2 x k16 steps ----
        const uint32_t sb = smem + SB_OFF + (t % 3) * B_STAGE;
        const int kg = kc * 32;
#pragma unroll
        for (int s = 0; s < 2; s++) {
            uint32_t b[4][2];
#pragma unroll
            for (int h = 0; h < 2; h++) {
                int nrow = wn * 32 + h * 16 + (lane & 7) + ((lane >> 4) & 1) * 8;
                int byt  = s * 32 + ((lane >> 3) & 1) * 16;
                uint32_t addr = sb + bswz(nrow, byt);
                uint32_t q0, q1, q2, q3;
                LDSM_X4(q0, q1, q2, q3, addr);
                b[2*h][0] = q0; b[2*h][1] = q1; b[2*h+1][0] = q2; b[2*h+1][1] = q3;
            }
#pragma unroll
            for (int mf = 0; mf < 2; mf++) {
                int r = wm * 32 + mf * 16 + (lane & 7) + ((lane >> 3) & 1) * 8;
                int kbyte = (kg + s * 16) * 2 + ((lane >> 4) & 1) * 16;
                uint32_t addr = smem + SA_OFF + r * A_ROW_BYTES + (kbyte ^ ((r & 7) << 4));
                uint32_t a0, a1, a2, a3;
                LDSM_X4(a0, a1, a2, a3, addr);
#pragma unroll
                for (int nf = 0; nf < 4; nf++)
                    MMA_16816(acc[mf][nf], a0, a1, a2, a3, b[nf][0], b[nf][1]);
            }
        }

        // ---- end of n-chunk: fold 128-code chunk into persistent top-2 ----
        if (kc == KCPN - 1) {
            const int nc = t / KCPN;
            const int colb = nc * 128 + wn * 32;
            float en[4][2];
#pragma unroll
            for (int nf = 0; nf < 4; nf++)
#pragma unroll
                for (int co = 0; co < 2; co++)
                    en[nf][co] = __ldg(&g_enorm[colb + nf * 8 + tig * 2 + co]);
#pragma unroll
            for (int mf = 0; mf < 2; mf++)
#pragma unroll
                for (int hf = 0; hf < 2; hf++) {
                    float v1 = tv1[mf][hf], v2 = tv2[mf][hf];
                    int   i1 = ti1[mf][hf], i2 = ti2[mf][hf];
#pragma unroll
                    for (int nf = 0; nf < 4; nf++)
#pragma unroll
                        for (int co = 0; co < 2; co++) {
                            float d = fmaf(-2.f, acc[mf][nf][hf * 2 + co], en[nf][co]);
                            int ix = colb + nf * 8 + tig * 2 + co;
                            if (d < v1 || (d == v1 && ix < i1)) {
                                v2 = v1; i2 = i1; v1 = d; i1 = ix;
                            } else if (d < v2 || (d == v2 && ix < i2)) {
                                v2 = d; i2 = ix;
                            }
                        }
                    tv1[mf][hf] = v1; tv2[mf][hf] = v2;
                    ti1[mf][hf] = i1; ti2[mf][hf] = i2;
                }
        }
    }

    // ---- final merge: across tig lanes, then across wn via SMEM ----
    __syncthreads();                 // all groups done; B stages now reusable
    float* pv = (float*)(smc + SB_OFF);
    int*   pi = (int*)(smc + SB_OFF + 4096);
#pragma unroll
    for (int mf = 0; mf < 2; mf++)
#pragma unroll
        for (int hf = 0; hf < 2; hf++) {
            float v1 = tv1[mf][hf], v2 = tv2[mf][hf];
            int   i1 = ti1[mf][hf], i2 = ti2[mf][hf];
#pragma unroll
            for (int off = 1; off < 4; off <<= 1) {
                float ov1 = __shfl_xor_sync(0xffffffffu, v1, off);
                int   oi1 = __shfl_xor_sync(0xffffffffu, i1, off);
                float ov2 = __shfl_xor_sync(0xffffffffu, v2, off);
                int   oi2 = __shfl_xor_sync(0xffffffffu, i2, off);
                if (ov1 < v1 || (ov1 == v1 && oi1 < i1)) {
                    v2 = v1; i2 = i1; v1 = ov1; i1 = oi1;
                } else if (ov1 < v2 || (ov1 == v2 && oi1 < i2)) {
                    v2 = ov1; i2 = oi1;
                }
                if (ov2 < v2 || (ov2 == v2 && oi2 < i2)) { v2 = ov2; i2 = oi2; }
            }
            if (tig == 0) {
                int row = wm * 32 + mf * 16 + hf * 8 + gid;
                pv[row * 8 + wn * 2 + 0] = v1;
                pi[row * 8 + wn * 2 + 0] = i1;
                pv[row * 8 + wn * 2 + 1] = v2;
                pi[row * 8 + wn * 2 + 1] = i2;
            }
        }
    __syncthreads();
    if (tid < 128) {
        float b1v = FLT_MAX, b2v = FLT_MAX;
        int   b1i = 0x7fffffff, b2i = 0x7fffffff;
#pragma unroll
        for (int w = 0; w < 8; w++) {
            float v = pv[tid * 8 + w];
            int   i = pi[tid * 8 + w];
            if (v < b1v || (v == b1v && i < b1i)) {
                b2v = b1v; b2i = b1i; b1v = v; b1i = i;
            } else if (v < b2v || (v == b2v && i < b2i)) {
                b2v = v; b2i = i;
            }
        }
        g_cand[rowBase + tid] = make_int2(b1i, b2i);
    }
}

// =====================================================================
// Kernel 4: exact fp32 rescore of the two candidates per row.
// Bit-identical arithmetic to the R1-passing kernel. Also writes the
// idx-as-float output slice (parallelized away from finalize).
// =====================================================================
__global__ __launch_bounds__(256)
void rescore_kernel(const float* __restrict__ inp, const float* __restrict__ emb,
                    float* __restrict__ out, int out_size) {
    int n = blockIdx.x * 256 + threadIdx.x;
    int b = n >> 10, rem = n & 1023;
    const float* fbase = inp + (size_t)b * CC * HWN + rem;
    int2 cand = g_cand[n];
    const float* e0 = emb + (size_t)cand.x * CC;
    const float* e1 = emb + (size_t)cand.y * CC;
    float dot0 = 0.f, dot1 = 0.f;
#pragma unroll 8
    for (int c = 0; c < CC; c++) {
        float f = __ldg(fbase + (size_t)c * HWN);
        dot0 = fmaf(f, __ldg(e0 + c), dot0);
        dot1 = fmaf(f, __ldg(e1 + c), dot1);
    }
    float d0 = fmaf(-2.f, dot0, g_enorm[cand.x]);
    float d1 = fmaf(-2.f, dot1, g_enorm[cand.y]);
    int win = cand.x;
    if (d1 < d0 || (d1 == d0 && cand.y < cand.x)) win = cand.y;
    g_idx[n] = win;
    if (out_size >= TOTAL_OUT)
        out[OUT_ELEMS + 1 + n] = (float)win;
}

// =====================================================================
// Kernel 5: gather quantized output + partial loss sums
// =====================================================================
__global__ __launch_bounds__(256)
void quant_kernel(const float* __restrict__ inp, const float* __restrict__ emb,
                  float* __restrict__ out) {
    __shared__ float red[256];
    const int tid = threadIdx.x;
    const int p4  = blockIdx.x * 256 + tid;
    const int p   = p4 * 4;
    const int rem = p & 1023;
    const int c   = (p >> 10) & 255;
    const int b   = p >> 18;
    const int n   = b * HWN + rem;

    float4 x = *(const float4*)(inp + p);
    int k0 = g_idx[n + 0], k1 = g_idx[n + 1], k2 = g_idx[n + 2], k3 = g_idx[n + 3];
    float q0 = __ldg(emb + (size_t)k0 * CC + c);
    float q1 = __ldg(emb + (size_t)k1 * CC + c);
    float q2 = __ldg(emb + (size_t)k2 * CC + c);
    float q3 = __ldg(emb + (size_t)k3 * CC + c);
    *(float4*)(out + p) = make_float4(q0, q1, q2, q3);

    float d0 = q0 - x.x, d1 = q1 - x.y, d2 = q2 - x.z, d3 = q3 - x.w;
    red[tid] = d0*d0 + d1*d1 + d2*d2 + d3*d3;
    __syncthreads();
#pragma unroll
    for (int sft = 128; sft; sft >>= 1) {
        if (tid < sft) red[tid] += red[tid + sft];
        __syncthreads();
    }
    if (tid == 0) g_partial[blockIdx.x] = red[0];
}

// =====================================================================
// Kernel 6: deterministic final reduce -> loss only
// =====================================================================
__global__ __launch_bounds__(256)
void finalize_kernel(float* __restrict__ out, int out_size) {
    __shared__ float red[256];
    const int tid = threadIdx.x;
    float s = 0.f;
#pragma unroll
    for (int i = 0; i < QUANT_BLOCKS / 256; i++) s += g_partial[tid + i * 256];
    red[tid] = s;
    __syncthreads();
#pragma unroll
    for (int sft = 128; sft; sft >>= 1) {
        if (tid < sft) red[tid] += red[tid + sft];
        __syncthreads();
    }
    if (tid == 0 && out_size >= OUT_ELEMS + 1)
        out[OUT_ELEMS] = 0.25f * red[0] / (float)OUT_ELEMS;
}

// =====================================================================
extern "C" void kernel_launch(void* const* d_in, const int* in_sizes, int n_in,
                              void* d_out, int out_size) {
    const float* inp = (const float*)d_in[0];
    const float* emb = (const float*)d_in[1];
    if (n_in >= 2 && in_sizes[0] == KK * CC && in_sizes[1] == NN * CC) {
        const float* t = inp; inp = emb; emb = t;
    }
    float* out = (float*)d_out;

    cudaFuncSetAttribute(vq_mma_kernel,
                         cudaFuncAttributeMaxDynamicSharedMemorySize, SMEM_TOTAL);

    emb_prep_kernel<<<KK / 8, 256>>>(emb);
    {
        dim3 g(NN / 32, CC / 32);
        conv_inp_kernel<<<g, 256>>>(inp);
    }
    vq_mma_kernel<<<NN / 128, 512, SMEM_TOTAL>>>();
    rescore_kernel<<<NN / 256, 256>>>(inp, emb, out, out_size);
    quant_kernel<<<QUANT_BLOCKS, 256>>>(inp, emb, out);
    finalize_kernel<<<1, 256>>>(out, out_size);
}

// round 7
// speedup vs baseline: 3.1942x; 1.3309x over previous
#include <cuda_runtime.h>
#include <cuda_bf16.h>
#include <float.h>
#include <stdint.h>

// ---------------- problem constants ----------------
#define BB   16
#define CC   256
#define HWN  1024
#define NN   16384            // input vectors
#define KK   8192             // codebook size
#define OUT_ELEMS 4194304
#define TOTAL_OUT (OUT_ELEMS + 1 + NN)
#define QUANT_BLOCKS 4096

#define NCHUNKS 64            // 8192 / 128 codes per chunk
#define KCPN 12               // k-chunks (64 wide) per n-chunk: 768/64
#define TCHUNKS (NCHUNKS * KCPN)   // 768

// ---------------- device scratch (no allocation allowed) ----------------
__device__ float g_enorm[KK];
__device__ int   g_idx[NN];
__device__ int2  g_cand[NN];
__device__ float g_partial[QUANT_BLOCKS];
__device__ __nv_bfloat16 g_eh[KK*CC], g_em[KK*CC];
__device__ __nv_bfloat16 g_ah[NN*CC], g_am[NN*CC];

// ---------------- PTX helpers (plain sm_103-legal only) ----------------
#define CP_ASYNC16(dst_u32, src_ptr) \
    asm volatile("cp.async.cg.shared.global [%0], [%1], 16;" \
        :: "r"(dst_u32), "l"(src_ptr) : "memory")
#define CP_COMMIT() asm volatile("cp.async.commit_group;" ::: "memory")
#define CP_WAIT(n)  asm volatile("cp.async.wait_group %0;" :: "n"(n) : "memory")

#define LDSM_X4(r0, r1, r2, r3, addr) \
    asm volatile("ldmatrix.sync.aligned.m8n8.x4.shared.b16 {%0,%1,%2,%3}, [%4];" \
        : "=r"(r0), "=r"(r1), "=r"(r2), "=r"(r3) : "r"(addr))

#define MMA_16816(c, a0, a1, a2, a3, b0, b1) \
    asm volatile("mma.sync.aligned.m16n8k16.row.col.f32.bf16.bf16.f32 " \
        "{%0,%1,%2,%3}, {%4,%5,%6,%7}, {%8,%9}, {%0,%1,%2,%3};" \
        : "+f"((c)[0]), "+f"((c)[1]), "+f"((c)[2]), "+f"((c)[3]) \
        : "r"(a0), "r"(a1), "r"(a2), "r"(a3), "r"(b0), "r"(b1))

#define GROUP_BAR(wn) \
    asm volatile("bar.sync %0, %1;" :: "r"((wn) + 1), "r"(128) : "memory")

// ---------------- SMEM layout ----------------
#define SA_OFF       0
#define A_ROW_BYTES  1536                      // 768 bf16, XOR-swizzled rows
#define SA_BYTES     (128 * A_ROW_BYTES)       // 196608
#define SB_OFF       SA_BYTES
#define B_ROW_BYTES  128                       // 64 bf16, 3-bit XOR swizzle
#define B_STAGE      (128 * B_ROW_BYTES)       // 16384
#define SMEM_TOTAL   (SB_OFF + 2 * B_STAGE)    // 229376 (< 232448 opt-in max)
// final merge partials reuse the B-stage area (B is dead by then)

__device__ __forceinline__ uint32_t bswz(int row, int byt) {
    return (uint32_t)(row * B_ROW_BYTES + (byt ^ ((row & 7) << 4)));
}

// =====================================================================
// Kernel 1: embedding prep — bf16 2-level split AND ||e_k||^2.
// =====================================================================
__global__ __launch_bounds__(256)
void emb_prep_kernel(const float* __restrict__ emb) {
    int row  = blockIdx.x * 8 + (threadIdx.x >> 5);
    int lane = threadIdx.x & 31;
    const float* e = emb + (size_t)row * CC;
    float s = 0.f;
#pragma unroll
    for (int i = 0; i < CC / 32; i++) {
        int c = lane + i * 32;
        float v = __ldg(e + c);
        s += v * v;
        __nv_bfloat16 h = __float2bfloat16(v);
        float r1 = v - __bfloat162float(h);
        __nv_bfloat16 m = __float2bfloat16(r1);
        size_t o = (size_t)row * CC + c;
        g_eh[o] = h; g_em[o] = m;
    }
#pragma unroll
    for (int off = 16; off; off >>= 1) s += __shfl_xor_sync(0xffffffffu, s, off);
    if (lane == 0) g_enorm[row] = s;
}

// =====================================================================
// Kernel 2: transpose inputs [B,C,HW] -> flat[n][c] + bf16 split
// =====================================================================
__global__ __launch_bounds__(256)
void conv_inp_kernel(const float* __restrict__ inp) {
    __shared__ float t[32][33];
    int n0 = blockIdx.x * 32;
    int c0 = blockIdx.y * 32;
    int b    = n0 >> 10;
    int rem0 = n0 & 1023;
    int tx = threadIdx.x & 31, ty = threadIdx.x >> 5;
#pragma unroll
    for (int i = 0; i < 4; i++) {
        int c = c0 + ty + i * 8;
        t[ty + i * 8][tx] = inp[(size_t)b * CC * HWN + (size_t)c * HWN + rem0 + tx];
    }
    __syncthreads();
#pragma unroll
    for (int i = 0; i < 4; i++) {
        int nl = ty + i * 8;
        int n = n0 + nl;
        float x = t[tx][nl];
        __nv_bfloat16 h = __float2bfloat16(x);
        float r1 = x - __bfloat162float(h);
        __nv_bfloat16 m = __float2bfloat16(r1);
        size_t o = (size_t)n * CC + c0 + tx;
        g_ah[o] = h; g_am[o] = m;
    }
}

// =====================================================================
// Kernel 3: fused mma.sync GEMM (K=768 bf16 split) + persistent top-2.
// 128 CTAs x 512 threads (16 warps). wm = warp&3 (SMSP), wn = warp>>2.
// B: 64-wide k-chunks, 2-stage cp.async ring, group-local load + named
// group barriers. 768 mainloop iterations, 32 MMAs per warp each.
// =====================================================================
__global__ __launch_bounds__(512, 1)
void vq_mma_kernel() {
    extern __shared__ char smc[];
    const uint32_t smem = (uint32_t)__cvta_generic_to_shared(smc);
    const int tid  = threadIdx.x;
    const int lane = tid & 31;
    const int warp = tid >> 5;
    const int wm = warp & 3;           // 0..3  (M direction, = SMSP)
    const int wn = warp >> 2;          // 0..3  (N direction, = group)
    const int gid = lane >> 2, tig = lane & 3;
    const int ltid = tid & 127;        // thread id within the group
    const int rowBase = blockIdx.x * 128;

    // ---- prologue: A tile fill (128 x 768 bf16, swizzled rows) ----
    for (int i = 0; i < 24; i++) {
        int id  = tid + i * 512;
        int r   = id & 127;
        int q   = id >> 7;                       // 0..95 : 16B chunk (8 k-elems)
        int seg = q >> 5;                        // 0,1 -> fh ; 2 -> fm
        const __nv_bfloat16* src =
            (seg == 2 ? g_am : g_ah) + (size_t)(rowBase + r) * CC + (q & 31) * 8;
        uint32_t dst = smem + SA_OFF + r * A_ROW_BYTES + ((q * 16) ^ ((r & 7) << 4));
        CP_ASYNC16(dst, src);
    }
    CP_COMMIT();

    // ---- group-local B prefetch: group wn loads rows [wn*32, wn*32+32) ----
    // chunk t: n-chunk t/12, k-chunk kc=t%12 (64 k wide)
    auto prefetchB = [&](int t) {
        int nc = t / KCPN, kc = t - nc * KCPN;
        int seg = kc >> 2;                       // 0:eh 1:em 2:eh
        const __nv_bfloat16* srcb = (seg == 1 ? g_em : g_eh);
        int kofs = (kc & 3) * 64;
        uint32_t sb = smem + SB_OFF + (t & 1) * B_STAGE;
        int n  = wn * 32 + (ltid >> 2);          // this group's slice
        int q0 = (ltid & 3) * 2;
#pragma unroll
        for (int j = 0; j < 2; j++) {
            int q = q0 + j;
            const __nv_bfloat16* src = srcb + (size_t)(nc * 128 + n) * CC + kofs + q * 8;
            CP_ASYNC16(sb + bswz(n, q * 16), src);
        }
    };
    prefetchB(0); CP_COMMIT();
    CP_WAIT(0);                 // A + B0 complete
    __syncthreads();            // A visible to all warps

    float acc[2][4][4];
    float tv1[2][2], tv2[2][2];
    int   ti1[2][2], ti2[2][2];
#pragma unroll
    for (int mf = 0; mf < 2; mf++)
#pragma unroll
        for (int hf = 0; hf < 2; hf++) {
            tv1[mf][hf] = FLT_MAX; tv2[mf][hf] = FLT_MAX;
            ti1[mf][hf] = 0x7fffffff; ti2[mf][hf] = 0x7fffffff;
        }

    for (int t = 0; t < TCHUNKS; t++) {
        if (t > 0) {
            CP_WAIT(0);          // chunk t's data landed
            GROUP_BAR(wn);       // group finished consuming buf[(t+1)&1]
        }
        if (t + 1 < TCHUNKS) { prefetchB(t + 1); CP_COMMIT(); }

        const int kc = t % KCPN;
        if (kc == 0) {
#pragma unroll
            for (int mf = 0; mf < 2; mf++)
#pragma unroll
                for (int nf = 0; nf < 4; nf++)
#pragma unroll
                    for (int e = 0; e < 4; e++) acc[mf][nf][e] = 0.f;
        }

        // ---- compute chunk t: 4 x k16 steps ----
        const uint32_t sb = smem + SB_OFF + (t & 1) * B_STAGE;
        const int kg = kc * 64;
#pragma unroll
        for (int s = 0; s < 4; s++) {
            uint32_t b[4][2];
#pragma unroll
            for (int h = 0; h < 2; h++) {
                int nrow = wn * 32 + h * 16 + (lane & 7) + ((lane >> 4) & 1) * 8;
                int byt  = s * 32 + ((lane >> 3) & 1) * 16;
                uint32_t addr = sb + bswz(nrow, byt);
                uint32_t q0, q1, q2, q3;
                LDSM_X4(q0, q1, q2, q3, addr);
                b[2*h][0] = q0; b[2*h][1] = q1; b[2*h+1][0] = q2; b[2*h+1][1] = q3;
            }
#pragma unroll
            for (int mf = 0; mf < 2; mf++) {
                int r = wm * 32 + mf * 16 + (lane & 7) + ((lane >> 3) & 1) * 8;
                int kbyte = (kg + s * 16) * 2 + ((lane >> 4) & 1) * 16;
                uint32_t addr = smem + SA_OFF + r * A_ROW_BYTES + (kbyte ^ ((r & 7) << 4));
                uint32_t a0, a1, a2, a3;
                LDSM_X4(a0, a1, a2, a3, addr);
#pragma unroll
                for (int nf = 0; nf < 4; nf++)
                    MMA_16816(acc[mf][nf], a0, a1, a2, a3, b[nf][0], b[nf][1]);
            }
        }

        // ---- end of n-chunk: fold 128-code chunk into persistent top-2 ----
        if (kc == KCPN - 1) {
            const int nc = t / KCPN;
            const int colb = nc * 128 + wn * 32;
            float en[4][2];
#pragma unroll
            for (int nf = 0; nf < 4; nf++)
#pragma unroll
                for (int co = 0; co < 2; co++)
                    en[nf][co] = __ldg(&g_enorm[colb + nf * 8 + tig * 2 + co]);
#pragma unroll
            for (int mf = 0; mf < 2; mf++)
#pragma unroll
                for (int hf = 0; hf < 2; hf++) {
                    float v1 = tv1[mf][hf], v2 = tv2[mf][hf];
                    int   i1 = ti1[mf][hf], i2 = ti2[mf][hf];
#pragma unroll
                    for (int nf = 0; nf < 4; nf++)
#pragma unroll
                        for (int co = 0; co < 2; co++) {
                            float d = fmaf(-2.f, acc[mf][nf][hf * 2 + co], en[nf][co]);
                            int ix = colb + nf * 8 + tig * 2 + co;
                            if (d < v1 || (d == v1 && ix < i1)) {
                                v2 = v1; i2 = i1; v1 = d; i1 = ix;
                            } else if (d < v2 || (d == v2 && ix < i2)) {
                                v2 = d; i2 = ix;
                            }
                        }
                    tv1[mf][hf] = v1; tv2[mf][hf] = v2;
                    ti1[mf][hf] = i1; ti2[mf][hf] = i2;
                }
        }
    }

    // ---- final merge: across tig lanes, then across wn via SMEM ----
    __syncthreads();                 // all groups done; B stages now reusable
    float* pv = (float*)(smc + SB_OFF);
    int*   pi = (int*)(smc + SB_OFF + 4096);
#pragma unroll
    for (int mf = 0; mf < 2; mf++)
#pragma unroll
        for (int hf = 0; hf < 2; hf++) {
            float v1 = tv1[mf][hf], v2 = tv2[mf][hf];
            int   i1 = ti1[mf][hf], i2 = ti2[mf][hf];
#pragma unroll
            for (int off = 1; off < 4; off <<= 1) {
                float ov1 = __shfl_xor_sync(0xffffffffu, v1, off);
                int   oi1 = __shfl_xor_sync(0xffffffffu, i1, off);
                float ov2 = __shfl_xor_sync(0xffffffffu, v2, off);
                int   oi2 = __shfl_xor_sync(0xffffffffu, i2, off);
                if (ov1 < v1 || (ov1 == v1 && oi1 < i1)) {
                    v2 = v1; i2 = i1; v1 = ov1; i1 = oi1;
                } else if (ov1 < v2 || (ov1 == v2 && oi1 < i2)) {
                    v2 = ov1; i2 = oi1;
                }
                if (ov2 < v2 || (ov2 == v2 && oi2 < i2)) { v2 = ov2; i2 = oi2; }
            }
            if (tig == 0) {
                int row = wm * 32 + mf * 16 + hf * 8 + gid;
                pv[row * 8 + wn * 2 + 0] = v1;
                pi[row * 8 + wn * 2 + 0] = i1;
                pv[row * 8 + wn * 2 + 1] = v2;
                pi[row * 8 + wn * 2 + 1] = i2;
            }
        }
    __syncthreads();
    if (tid < 128) {
        float b1v = FLT_MAX, b2v = FLT_MAX;
        int   b1i = 0x7fffffff, b2i = 0x7fffffff;
#pragma unroll
        for (int w = 0; w < 8; w++) {
            float v = pv[tid * 8 + w];
            int   i = pi[tid * 8 + w];
            if (v < b1v || (v == b1v && i < b1i)) {
                b2v = b1v; b2i = b1i; b1v = v; b1i = i;
            } else if (v < b2v || (v == b2v && i < b2i)) {
                b2v = v; b2i = i;
            }
        }
        g_cand[rowBase + tid] = make_int2(b1i, b2i);
    }
}

// =====================================================================
// Kernel 4: exact fp32 rescore (sequential fmaf chain, same order as
// the R1-exact kernel; float4 loads don't change the arithmetic).
// 128 blocks x 128 threads for full-chip occupancy.
// =====================================================================
__global__ __launch_bounds__(128)
void rescore_kernel(const float* __restrict__ inp, const float* __restrict__ emb,
                    float* __restrict__ out, int out_size) {
    int n = blockIdx.x * 128 + threadIdx.x;
    int b = n >> 10, rem = n & 1023;
    const float* fbase = inp + (size_t)b * CC * HWN + rem;
    int2 cand = g_cand[n];
    const float4* e0 = (const float4*)(emb + (size_t)cand.x * CC);
    const float4* e1 = (const float4*)(emb + (size_t)cand.y * CC);
    float dot0 = 0.f, dot1 = 0.f;
#pragma unroll 8
    for (int c4 = 0; c4 < CC / 4; c4++) {
        float4 v0 = __ldg(e0 + c4);
        float4 v1 = __ldg(e1 + c4);
        float f0 = __ldg(fbase + (size_t)(c4 * 4 + 0) * HWN);
        float f1 = __ldg(fbase + (size_t)(c4 * 4 + 1) * HWN);
        float f2 = __ldg(fbase + (size_t)(c4 * 4 + 2) * HWN);
        float f3 = __ldg(fbase + (size_t)(c4 * 4 + 3) * HWN);
        dot0 = fmaf(f0, v0.x, dot0); dot1 = fmaf(f0, v1.x, dot1);
        dot0 = fmaf(f1, v0.y, dot0); dot1 = fmaf(f1, v1.y, dot1);
        dot0 = fmaf(f2, v0.z, dot0); dot1 = fmaf(f2, v1.z, dot1);
        dot0 = fmaf(f3, v0.w, dot0); dot1 = fmaf(f3, v1.w, dot1);
    }
    float d0 = fmaf(-2.f, dot0, g_enorm[cand.x]);
    float d1 = fmaf(-2.f, dot1, g_enorm[cand.y]);
    int win = cand.x;
    if (d1 < d0 || (d1 == d0 && cand.y < cand.x)) win = cand.y;
    g_idx[n] = win;
    if (out_size >= TOTAL_OUT)
        out[OUT_ELEMS + 1 + n] = (float)win;
}

// =====================================================================
// Kernel 5: gather quantized output + partial loss sums
// =====================================================================
__global__ __launch_bounds__(256)
void quant_kernel(const float* __restrict__ inp, const float* __restrict__ emb,
                  float* __restrict__ out) {
    __shared__ float red[256];
    const int tid = threadIdx.x;
    const int p4  = blockIdx.x * 256 + tid;
    const int p   = p4 * 4;
    const int rem = p & 1023;
    const int c   = (p >> 10) & 255;
    const int b   = p >> 18;
    const int n   = b * HWN + rem;

    float4 x = *(const float4*)(inp + p);
    int k0 = g_idx[n + 0], k1 = g_idx[n + 1], k2 = g_idx[n + 2], k3 = g_idx[n + 3];
    float q0 = __ldg(emb + (size_t)k0 * CC + c);
    float q1 = __ldg(emb + (size_t)k1 * CC + c);
    float q2 = __ldg(emb + (size_t)k2 * CC + c);
    float q3 = __ldg(emb + (size_t)k3 * CC + c);
    *(float4*)(out + p) = make_float4(q0, q1, q2, q3);

    float d0 = q0 - x.x, d1 = q1 - x.y, d2 = q2 - x.z, d3 = q3 - x.w;
    red[tid] = d0*d0 + d1*d1 + d2*d2 + d3*d3;
    __syncthreads();
#pragma unroll
    for (int sft = 128; sft; sft >>= 1) {
        if (tid < sft) red[tid] += red[tid + sft];
        __syncthreads();
    }
    if (tid == 0) g_partial[blockIdx.x] = red[0];
}

// =====================================================================
// Kernel 6: deterministic final reduce -> loss only
// =====================================================================
__global__ __launch_bounds__(256)
void finalize_kernel(float* __restrict__ out, int out_size) {
    __shared__ float red[256];
    const int tid = threadIdx.x;
    float s = 0.f;
#pragma unroll
    for (int i = 0; i < QUANT_BLOCKS / 256; i++) s += g_partial[tid + i * 256];
    red[tid] = s;
    __syncthreads();
#pragma unroll
    for (int sft = 128; sft; sft >>= 1) {
        if (tid < sft) red[tid] += red[tid + sft];
        __syncthreads();
    }
    if (tid == 0 && out_size >= OUT_ELEMS + 1)
        out[OUT_ELEMS] = 0.25f * red[0] / (float)OUT_ELEMS;
}

// =====================================================================
extern "C" void kernel_launch(void* const* d_in, const int* in_sizes, int n_in,
                              void* d_out, int out_size) {
    const float* inp = (const float*)d_in[0];
    const float* emb = (const float*)d_in[1];
    if (n_in >= 2 && in_sizes[0] == KK * CC && in_sizes[1] == NN * CC) {
        const float* t = inp; inp = emb; emb = t;
    }
    float* out = (float*)d_out;

    cudaFuncSetAttribute(vq_mma_kernel,
                         cudaFuncAttributeMaxDynamicSharedMemorySize, SMEM_TOTAL);

    emb_prep_kernel<<<KK / 8, 256>>>(emb);
    {
        dim3 g(NN / 32, CC / 32);
        conv_inp_kernel<<<g, 256>>>(inp);
    }
    vq_mma_kernel<<<NN / 128, 512, SMEM_TOTAL>>>();
    rescore_kernel<<<NN / 128, 128>>>(inp, emb, out, out_size);
    quant_kernel<<<QUANT_BLOCKS, 256>>>(inp, emb, out);
    finalize_kernel<<<1, 256>>>(out, out_size);
}